// round 11
// baseline (speedup 1.0000x reference)
#include <cuda_runtime.h>
#include <cuda_bf16.h>
#include <cstdint>
#include <cstddef>

#define N0 2000000
#define N1 200000
#define N2 16384
#define E0 3200000
#define E1 262144

// Scratch (device globals: allocation-free rule)
__device__ __nv_bfloat16 g_y[(size_t)N0 * 32];   // 128 MB, bf16-compressed
__device__ float g_h[(size_t)N1 * 32];
__device__ float g_agg0[(size_t)N1 * 32];
__device__ float g_agg1[(size_t)N2 * 32];
__device__ float g_cnt0[N1];
__device__ float g_cnt1[N2];

// pack two f32 -> bf16x2 word: low half = first arg, high half = second arg
__device__ __forceinline__ uint32_t pack_bf16x2(float lo, float hi) {
    uint32_t r;
    asm("cvt.rn.bf16x2.f32 %0, %1, %2;" : "=r"(r) : "f"(hi), "f"(lo));
    return r;
}
__device__ __forceinline__ float bf_lo(uint32_t w) { return __uint_as_float(w << 16); }
__device__ __forceinline__ float bf_hi(uint32_t w) { return __uint_as_float(w & 0xffff0000u); }

// D(16x8,f32) += A(16x16,bf16 row) * B(16x8,bf16 col)
__device__ __forceinline__ void mma16816(float* c, const uint32_t* a, const uint32_t* b) {
    asm volatile(
        "mma.sync.aligned.m16n8k16.row.col.f32.bf16.bf16.f32 "
        "{%0,%1,%2,%3}, {%4,%5,%6,%7}, {%8,%9}, {%0,%1,%2,%3};"
        : "+f"(c[0]), "+f"(c[1]), "+f"(c[2]), "+f"(c[3])
        : "r"(a[0]), "r"(a[1]), "r"(a[2]), "r"(a[3]), "r"(b[0]), "r"(b[1]));
}

// ---------------- HMMA GEMM: out[m,0..31] = x[m,0..127] @ W^T ----------------
// K-slot permutation: thread tig's k-slots (2t,2t+1,2t+8,2t+9) hold ACTUAL
// columns 4t..4t+3 (same permutation on A and B) -> A fragment = one LDG.128.
// bf16 split: keep hi*hi + hi*lo + lo*hi (~4e-6 rel err).
// mode 0: write bf16 y.  mode 1: out = relu(acc + agg/cnt) in fp32.
__global__ void __launch_bounds__(256) gemm_mma_kernel(
    const float* __restrict__ x, const float* __restrict__ W, int M,
    __nv_bfloat16* __restrict__ obf, float* __restrict__ out, int mode,
    const float* __restrict__ agg, const float* __restrict__ cnt)
{
    __shared__ uint32_t sBhi[8][4][32][2];   // 8 KB
    __shared__ uint32_t sBlo[8][4][32][2];   // 8 KB

    const int tid = threadIdx.x;
    const int warp = tid >> 5, lane = tid & 31;
    const int gid = lane >> 2, tig = lane & 3;

    // Build B fragments (permuted): lane l -> n = nt*8 + (l>>2), k0 = kt*16 + (l&3)*4
    for (int i = tid; i < 1024; i += 256) {
        int l = i & 31, nt = (i >> 5) & 3, kt = i >> 7;
        int n = nt * 8 + (l >> 2);
        int k0 = kt * 16 + (l & 3) * 4;
        float4 w = *reinterpret_cast<const float4*>(W + n * 128 + k0);
        uint32_t h0 = pack_bf16x2(w.x, w.y);
        uint32_t h1 = pack_bf16x2(w.z, w.w);
        sBhi[kt][nt][l][0] = h0;
        sBhi[kt][nt][l][1] = h1;
        sBlo[kt][nt][l][0] = pack_bf16x2(w.x - bf_lo(h0), w.y - bf_hi(h0));
        sBlo[kt][nt][l][1] = pack_bf16x2(w.z - bf_lo(h1), w.w - bf_hi(h1));
    }
    __syncthreads();

    int r0 = blockIdx.x * 128 + warp * 16 + gid;
    int r1 = r0 + 8;
    int r0c = r0 < M ? r0 : M - 1;
    int r1c = r1 < M ? r1 : M - 1;
    const float* x0 = x + (size_t)r0c * 128;
    const float* x1 = x + (size_t)r1c * 128;

    float acc[4][4];
#pragma unroll
    for (int nt = 0; nt < 4; ++nt)
#pragma unroll
        for (int j = 0; j < 4; ++j) acc[nt][j] = 0.f;

#pragma unroll
    for (int kt = 0; kt < 8; ++kt) {
        int c0 = kt * 16 + tig * 4;
        float4 f0 = *reinterpret_cast<const float4*>(x0 + c0);
        float4 f1 = *reinterpret_cast<const float4*>(x1 + c0);

        uint32_t ahi[4], alo[4];
        ahi[0] = pack_bf16x2(f0.x, f0.y);
        ahi[1] = pack_bf16x2(f1.x, f1.y);
        ahi[2] = pack_bf16x2(f0.z, f0.w);
        ahi[3] = pack_bf16x2(f1.z, f1.w);
        alo[0] = pack_bf16x2(f0.x - bf_lo(ahi[0]), f0.y - bf_hi(ahi[0]));
        alo[1] = pack_bf16x2(f1.x - bf_lo(ahi[1]), f1.y - bf_hi(ahi[1]));
        alo[2] = pack_bf16x2(f0.z - bf_lo(ahi[2]), f0.w - bf_hi(ahi[2]));
        alo[3] = pack_bf16x2(f1.z - bf_lo(ahi[3]), f1.w - bf_hi(ahi[3]));

#pragma unroll
        for (int nt = 0; nt < 4; ++nt) {
            uint32_t bh[2], bl[2];
            bh[0] = sBhi[kt][nt][lane][0];
            bh[1] = sBhi[kt][nt][lane][1];
            bl[0] = sBlo[kt][nt][lane][0];
            bl[1] = sBlo[kt][nt][lane][1];
            mma16816(acc[nt], ahi, bh);
            mma16816(acc[nt], ahi, bl);
            mma16816(acc[nt], alo, bh);
        }
    }

    // Epilogue. D frag: c0,c1 -> (r0, nt*8+tig*2..+1); c2,c3 -> (r1, same cols)
    if (mode == 0) {
        // bf16 store: each (row, nt) pair -> one uint32 (2 bf16) at col tig*2 + nt*8
        if (r0 < M) {
            uint32_t* o = reinterpret_cast<uint32_t*>(obf + (size_t)r0 * 32) + tig;
#pragma unroll
            for (int nt = 0; nt < 4; ++nt)
                o[nt * 4] = pack_bf16x2(acc[nt][0], acc[nt][1]);
        }
        if (r1 < M) {
            uint32_t* o = reinterpret_cast<uint32_t*>(obf + (size_t)r1 * 32) + tig;
#pragma unroll
            for (int nt = 0; nt < 4; ++nt)
                o[nt * 4] = pack_bf16x2(acc[nt][2], acc[nt][3]);
        }
    } else {
        if (r0 < M) {
            float inv = 1.0f / fmaxf(__ldg(cnt + r0), 1.0f);
            const float* g = agg + (size_t)r0 * 32 + tig * 2;
            float* o = out + (size_t)r0 * 32 + tig * 2;
#pragma unroll
            for (int nt = 0; nt < 4; ++nt) {
                float2 a = *reinterpret_cast<const float2*>(g + nt * 8);
                float2 v;
                v.x = fmaxf(fmaf(a.x, inv, acc[nt][0]), 0.f);
                v.y = fmaxf(fmaf(a.y, inv, acc[nt][1]), 0.f);
                *reinterpret_cast<float2*>(o + nt * 8) = v;
            }
        }
        if (r1 < M) {
            float inv = 1.0f / fmaxf(__ldg(cnt + r1), 1.0f);
            const float* g = agg + (size_t)r1 * 32 + tig * 2;
            float* o = out + (size_t)r1 * 32 + tig * 2;
#pragma unroll
            for (int nt = 0; nt < 4; ++nt) {
                float2 a = *reinterpret_cast<const float2*>(g + nt * 8);
                float2 v;
                v.x = fmaxf(fmaf(a.x, inv, acc[nt][2]), 0.f);
                v.y = fmaxf(fmaf(a.y, inv, acc[nt][3]), 0.f);
                *reinterpret_cast<float2*>(o + nt * 8) = v;
            }
        }
    }
}

// ---------------- bf16 edge scatter (4 threads/edge, 4-edge MLP) ----------------
// feat rows are 32 bf16 (64 B). Each thread moves 8 cols (uint4 = 16 B).
__global__ void scatter_bf16_kernel(const int* __restrict__ src, const int* __restrict__ dst,
                                    const __nv_bfloat16* __restrict__ feat,
                                    float* __restrict__ agg, float* __restrict__ cnt, int E) {
    int g = blockIdx.x * blockDim.x + threadIdx.x;
    int quart = E >> 2;
    int e = g >> 2, part = g & 3;
    if (e >= quart) return;
    int s[4], d[4];
#pragma unroll
    for (int j = 0; j < 4; ++j) {
        s[j] = __ldg(src + e + j * quart);
        d[j] = __ldg(dst + e + j * quart);
    }
    uint4 v[4];
#pragma unroll
    for (int j = 0; j < 4; ++j)
        v[j] = reinterpret_cast<const uint4*>(feat + (size_t)s[j] * 32)[part];
#pragma unroll
    for (int j = 0; j < 4; ++j) {
        float4 lo4 = make_float4(bf_lo(v[j].x), bf_hi(v[j].x), bf_lo(v[j].y), bf_hi(v[j].y));
        float4 hi4 = make_float4(bf_lo(v[j].z), bf_hi(v[j].z), bf_lo(v[j].w), bf_hi(v[j].w));
        float* base = agg + (size_t)d[j] * 32 + part * 8;
        atomicAdd(reinterpret_cast<float4*>(base), lo4);
        atomicAdd(reinterpret_cast<float4*>(base + 4), hi4);
    }
    if (part == 0) {
#pragma unroll
        for (int j = 0; j < 4; ++j) atomicAdd(cnt + d[j], 1.0f);
    }
}

// ---------------- fp32 edge scatter (8 threads/edge, 4-edge MLP) — for h/E1 ----------------
__global__ void scatter_kernel(const int* __restrict__ src, const int* __restrict__ dst,
                               const float* __restrict__ feat, float* __restrict__ agg,
                               float* __restrict__ cnt, int E) {
    int g = blockIdx.x * blockDim.x + threadIdx.x;
    int quart = E >> 2;
    int e = g >> 3, part = g & 7;
    if (e >= quart) return;
    int s[4], d[4];
#pragma unroll
    for (int j = 0; j < 4; ++j) {
        s[j] = __ldg(src + e + j * quart);
        d[j] = __ldg(dst + e + j * quart);
    }
    float4 v[4];
#pragma unroll
    for (int j = 0; j < 4; ++j)
        v[j] = *reinterpret_cast<const float4*>(feat + (size_t)s[j] * 32 + part * 4);
#pragma unroll
    for (int j = 0; j < 4; ++j)
        atomicAdd(reinterpret_cast<float4*>(agg + (size_t)d[j] * 32 + part * 4), v[j]);
    if (part == 0) {
#pragma unroll
        for (int j = 0; j < 4; ++j) atomicAdd(cnt + d[j], 1.0f);
    }
}

// ---------------- layer-1 combine ----------------
__global__ void final_kernel(const float* __restrict__ agg1, const float* __restrict__ cnt1,
                             const float* __restrict__ h, const float* __restrict__ W2l,
                             const float* __restrict__ W2r, float* __restrict__ out) {
    __shared__ float s2l[32 * 64];
    __shared__ float s2r[32 * 64];
    int tid = threadIdx.x;
    for (int idx = tid; idx < 2048; idx += 256) {
        int c = idx >> 5, k = idx & 31;
        s2l[k * 64 + c] = W2l[idx];
        s2r[k * 64 + c] = W2r[idx];
    }
    __syncthreads();
    int i = blockIdx.x * 4 + (tid >> 6);
    int c = tid & 63;
    float inv = 1.0f / fmaxf(__ldg(cnt1 + i), 1.0f);
    const float* ag = agg1 + (size_t)i * 32;
    const float* hh = h + (size_t)i * 32;
    float s = 0.f;
#pragma unroll
    for (int k = 0; k < 32; ++k)
        s = fmaf(__ldg(ag + k) * inv, s2l[k * 64 + c], fmaf(__ldg(hh + k), s2r[k * 64 + c], s));
    out[(size_t)i * 64 + c] = s;
}

__global__ void noop_kernel() {}

extern "C" void kernel_launch(void* const* d_in, const int* in_sizes, int n_in,
                              void* d_out, int out_size) {
    const float* x   = (const float*)d_in[0];
    const float* W1l = (const float*)d_in[1];
    const float* W1r = (const float*)d_in[2];
    const float* W2l = (const float*)d_in[3];
    const float* W2r = (const float*)d_in[4];
    const int* es0   = (const int*)d_in[5];
    const int* ed0   = (const int*)d_in[6];
    const int* es1   = (const int*)d_in[7];
    const int* ed1   = (const int*)d_in[8];
    float* out = (float*)d_out;

    __nv_bfloat16* y;
    float *h, *agg0, *agg1, *cnt0, *cnt1;
    cudaGetSymbolAddress((void**)&y,    g_y);
    cudaGetSymbolAddress((void**)&h,    g_h);
    cudaGetSymbolAddress((void**)&agg0, g_agg0);
    cudaGetSymbolAddress((void**)&agg1, g_agg1);
    cudaGetSymbolAddress((void**)&cnt0, g_cnt0);
    cudaGetSymbolAddress((void**)&cnt1, g_cnt1);

    cudaMemsetAsync(agg0, 0, sizeof(float) * (size_t)N1 * 32, 0);
    cudaMemsetAsync(cnt0, 0, sizeof(float) * N1, 0);
    cudaMemsetAsync(agg1, 0, sizeof(float) * (size_t)N2 * 32, 0);
    cudaMemsetAsync(cnt1, 0, sizeof(float) * N2, 0);

    // kernel-launch order: #0,#1 noop, #2 gemm(N0), #3 scatter_bf16(E0) <- profiled
    noop_kernel<<<1, 32>>>();
    noop_kernel<<<1, 32>>>();

    gemm_mma_kernel<<<(N0 + 127) / 128, 256>>>(x, W1l, N0, y, nullptr, 0, nullptr, nullptr);
    scatter_bf16_kernel<<<(int)(((size_t)E0 + 255) / 256), 256>>>(es0, ed0, y, agg0, cnt0, E0);
    gemm_mma_kernel<<<(N1 + 127) / 128, 256>>>(x, W1r, N1, nullptr, h, 1, agg0, cnt0);
    scatter_kernel<<<(int)(((size_t)(E1 / 4) * 8 + 255) / 256), 256>>>(es1, ed1, h, agg1, cnt1, E1);
    final_kernel<<<N2 / 4, 256>>>(agg1, cnt1, h, W2l, W2r, out);
}

// round 12
// speedup vs baseline: 1.0839x; 1.0839x over previous
#include <cuda_runtime.h>
#include <cuda_bf16.h>
#include <cstdint>
#include <cstddef>

#define N0 2000000
#define N1 200000
#define N2 16384
#define E0 3200000
#define E1 262144

// Scratch (device globals: allocation-free rule)
__device__ __nv_bfloat16 g_y[(size_t)N0 * 32];   // 128 MB, bf16-compressed
__device__ float g_h[(size_t)N1 * 32];
__device__ float g_agg0[(size_t)N1 * 32];
__device__ float g_agg1[(size_t)N2 * 32];
__device__ float g_cnt0[N1];
__device__ float g_cnt1[N2];

// pack two f32 -> bf16x2 word: low half = first arg, high half = second arg
__device__ __forceinline__ uint32_t pack_bf16x2(float lo, float hi) {
    uint32_t r;
    asm("cvt.rn.bf16x2.f32 %0, %1, %2;" : "=r"(r) : "f"(hi), "f"(lo));
    return r;
}
__device__ __forceinline__ float bf_lo(uint32_t w) { return __uint_as_float(w << 16); }
__device__ __forceinline__ float bf_hi(uint32_t w) { return __uint_as_float(w & 0xffff0000u); }

// D(16x8,f32) += A(16x16,bf16 row) * B(16x8,bf16 col)
__device__ __forceinline__ void mma16816(float* c, const uint32_t* a, const uint32_t* b) {
    asm volatile(
        "mma.sync.aligned.m16n8k16.row.col.f32.bf16.bf16.f32 "
        "{%0,%1,%2,%3}, {%4,%5,%6,%7}, {%8,%9}, {%0,%1,%2,%3};"
        : "+f"(c[0]), "+f"(c[1]), "+f"(c[2]), "+f"(c[3])
        : "r"(a[0]), "r"(a[1]), "r"(a[2]), "r"(a[3]), "r"(b[0]), "r"(b[1]));
}

// ---------------- HMMA GEMM: out[m,0..31] = x[m,0..127] @ W^T ----------------
// K-slot permutation: thread tig's k-slots (2t,2t+1,2t+8,2t+9) hold ACTUAL
// columns 4t..4t+3 (same permutation on A and B) -> A fragment = one LDG.128.
// bf16 split: keep hi*hi + hi*lo + lo*hi (~4e-6 rel err).
// mode 0: write bf16 y.  mode 1: out = relu(acc + agg/cnt) in fp32.
__global__ void __launch_bounds__(256) gemm_mma_kernel(
    const float* __restrict__ x, const float* __restrict__ W, int M,
    __nv_bfloat16* __restrict__ obf, float* __restrict__ out, int mode,
    const float* __restrict__ agg, const float* __restrict__ cnt)
{
    __shared__ uint32_t sBhi[8][4][32][2];   // 8 KB
    __shared__ uint32_t sBlo[8][4][32][2];   // 8 KB

    const int tid = threadIdx.x;
    const int warp = tid >> 5, lane = tid & 31;
    const int gid = lane >> 2, tig = lane & 3;

    // Build B fragments (permuted): lane l -> n = nt*8 + (l>>2), k0 = kt*16 + (l&3)*4
    for (int i = tid; i < 1024; i += 256) {
        int l = i & 31, nt = (i >> 5) & 3, kt = i >> 7;
        int n = nt * 8 + (l >> 2);
        int k0 = kt * 16 + (l & 3) * 4;
        float4 w = *reinterpret_cast<const float4*>(W + n * 128 + k0);
        uint32_t h0 = pack_bf16x2(w.x, w.y);
        uint32_t h1 = pack_bf16x2(w.z, w.w);
        sBhi[kt][nt][l][0] = h0;
        sBhi[kt][nt][l][1] = h1;
        sBlo[kt][nt][l][0] = pack_bf16x2(w.x - bf_lo(h0), w.y - bf_hi(h0));
        sBlo[kt][nt][l][1] = pack_bf16x2(w.z - bf_lo(h1), w.w - bf_hi(h1));
    }
    __syncthreads();

    int r0 = blockIdx.x * 128 + warp * 16 + gid;
    int r1 = r0 + 8;
    int r0c = r0 < M ? r0 : M - 1;
    int r1c = r1 < M ? r1 : M - 1;
    const float* x0 = x + (size_t)r0c * 128;
    const float* x1 = x + (size_t)r1c * 128;

    float acc[4][4];
#pragma unroll
    for (int nt = 0; nt < 4; ++nt)
#pragma unroll
        for (int j = 0; j < 4; ++j) acc[nt][j] = 0.f;

#pragma unroll
    for (int kt = 0; kt < 8; ++kt) {
        int c0 = kt * 16 + tig * 4;
        float4 f0 = *reinterpret_cast<const float4*>(x0 + c0);
        float4 f1 = *reinterpret_cast<const float4*>(x1 + c0);

        uint32_t ahi[4], alo[4];
        ahi[0] = pack_bf16x2(f0.x, f0.y);
        ahi[1] = pack_bf16x2(f1.x, f1.y);
        ahi[2] = pack_bf16x2(f0.z, f0.w);
        ahi[3] = pack_bf16x2(f1.z, f1.w);
        alo[0] = pack_bf16x2(f0.x - bf_lo(ahi[0]), f0.y - bf_hi(ahi[0]));
        alo[1] = pack_bf16x2(f1.x - bf_lo(ahi[1]), f1.y - bf_hi(ahi[1]));
        alo[2] = pack_bf16x2(f0.z - bf_lo(ahi[2]), f0.w - bf_hi(ahi[2]));
        alo[3] = pack_bf16x2(f1.z - bf_lo(ahi[3]), f1.w - bf_hi(ahi[3]));

#pragma unroll
        for (int nt = 0; nt < 4; ++nt) {
            uint32_t bh[2], bl[2];
            bh[0] = sBhi[kt][nt][lane][0];
            bh[1] = sBhi[kt][nt][lane][1];
            bl[0] = sBlo[kt][nt][lane][0];
            bl[1] = sBlo[kt][nt][lane][1];
            mma16816(acc[nt], ahi, bh);
            mma16816(acc[nt], ahi, bl);
            mma16816(acc[nt], alo, bh);
        }
    }

    // Epilogue. D frag: c0,c1 -> (r0, nt*8+tig*2..+1); c2,c3 -> (r1, same cols)
    if (mode == 0) {
        if (r0 < M) {
            uint32_t* o = reinterpret_cast<uint32_t*>(obf + (size_t)r0 * 32) + tig;
#pragma unroll
            for (int nt = 0; nt < 4; ++nt)
                o[nt * 4] = pack_bf16x2(acc[nt][0], acc[nt][1]);
        }
        if (r1 < M) {
            uint32_t* o = reinterpret_cast<uint32_t*>(obf + (size_t)r1 * 32) + tig;
#pragma unroll
            for (int nt = 0; nt < 4; ++nt)
                o[nt * 4] = pack_bf16x2(acc[nt][2], acc[nt][3]);
        }
    } else {
        if (r0 < M) {
            float inv = 1.0f / fmaxf(__ldg(cnt + r0), 1.0f);
            const float* g = agg + (size_t)r0 * 32 + tig * 2;
            float* o = out + (size_t)r0 * 32 + tig * 2;
#pragma unroll
            for (int nt = 0; nt < 4; ++nt) {
                float2 a = *reinterpret_cast<const float2*>(g + nt * 8);
                float2 v;
                v.x = fmaxf(fmaf(a.x, inv, acc[nt][0]), 0.f);
                v.y = fmaxf(fmaf(a.y, inv, acc[nt][1]), 0.f);
                *reinterpret_cast<float2*>(o + nt * 8) = v;
            }
        }
        if (r1 < M) {
            float inv = 1.0f / fmaxf(__ldg(cnt + r1), 1.0f);
            const float* g = agg + (size_t)r1 * 32 + tig * 2;
            float* o = out + (size_t)r1 * 32 + tig * 2;
#pragma unroll
            for (int nt = 0; nt < 4; ++nt) {
                float2 a = *reinterpret_cast<const float2*>(g + nt * 8);
                float2 v;
                v.x = fmaxf(fmaf(a.x, inv, acc[nt][2]), 0.f);
                v.y = fmaxf(fmaf(a.y, inv, acc[nt][3]), 0.f);
                *reinterpret_cast<float2*>(o + nt * 8) = v;
            }
        }
    }
}

// ---------------- bf16 edge scatter: 8 threads/edge, 4-edge MLP ----------------
// Same shape as the 102us fp32 scatter: 1 load + 1 float4 atomic per edge-part,
// but the gather load is uint2 (4 bf16, 8 B) -> half the random-line bytes.
__global__ void scatter_bf16_kernel(const int* __restrict__ src, const int* __restrict__ dst,
                                    const __nv_bfloat16* __restrict__ feat,
                                    float* __restrict__ agg, float* __restrict__ cnt, int E) {
    int g = blockIdx.x * blockDim.x + threadIdx.x;
    int quart = E >> 2;
    int e = g >> 3, part = g & 7;
    if (e >= quart) return;
    int s[4], d[4];
#pragma unroll
    for (int j = 0; j < 4; ++j) {
        s[j] = __ldg(src + e + j * quart);
        d[j] = __ldg(dst + e + j * quart);
    }
    uint2 v[4];
#pragma unroll
    for (int j = 0; j < 4; ++j)
        v[j] = reinterpret_cast<const uint2*>(feat + (size_t)s[j] * 32)[part];
#pragma unroll
    for (int j = 0; j < 4; ++j) {
        float4 f = make_float4(bf_lo(v[j].x), bf_hi(v[j].x), bf_lo(v[j].y), bf_hi(v[j].y));
        atomicAdd(reinterpret_cast<float4*>(agg + (size_t)d[j] * 32 + part * 4), f);
    }
    if (part == 0) {
#pragma unroll
        for (int j = 0; j < 4; ++j) atomicAdd(cnt + d[j], 1.0f);
    }
}

// ---------------- fp32 edge scatter (8 threads/edge, 4-edge MLP) — for h/E1 ----------------
__global__ void scatter_kernel(const int* __restrict__ src, const int* __restrict__ dst,
                               const float* __restrict__ feat, float* __restrict__ agg,
                               float* __restrict__ cnt, int E) {
    int g = blockIdx.x * blockDim.x + threadIdx.x;
    int quart = E >> 2;
    int e = g >> 3, part = g & 7;
    if (e >= quart) return;
    int s[4], d[4];
#pragma unroll
    for (int j = 0; j < 4; ++j) {
        s[j] = __ldg(src + e + j * quart);
        d[j] = __ldg(dst + e + j * quart);
    }
    float4 v[4];
#pragma unroll
    for (int j = 0; j < 4; ++j)
        v[j] = *reinterpret_cast<const float4*>(feat + (size_t)s[j] * 32 + part * 4);
#pragma unroll
    for (int j = 0; j < 4; ++j)
        atomicAdd(reinterpret_cast<float4*>(agg + (size_t)d[j] * 32 + part * 4), v[j]);
    if (part == 0) {
#pragma unroll
        for (int j = 0; j < 4; ++j) atomicAdd(cnt + d[j], 1.0f);
    }
}

// ---------------- layer-1 combine ----------------
__global__ void final_kernel(const float* __restrict__ agg1, const float* __restrict__ cnt1,
                             const float* __restrict__ h, const float* __restrict__ W2l,
                             const float* __restrict__ W2r, float* __restrict__ out) {
    __shared__ float s2l[32 * 64];
    __shared__ float s2r[32 * 64];
    int tid = threadIdx.x;
    for (int idx = tid; idx < 2048; idx += 256) {
        int c = idx >> 5, k = idx & 31;
        s2l[k * 64 + c] = W2l[idx];
        s2r[k * 64 + c] = W2r[idx];
    }
    __syncthreads();
    int i = blockIdx.x * 4 + (tid >> 6);
    int c = tid & 63;
    float inv = 1.0f / fmaxf(__ldg(cnt1 + i), 1.0f);
    const float* ag = agg1 + (size_t)i * 32;
    const float* hh = h + (size_t)i * 32;
    float s = 0.f;
#pragma unroll
    for (int k = 0; k < 32; ++k)
        s = fmaf(__ldg(ag + k) * inv, s2l[k * 64 + c], fmaf(__ldg(hh + k), s2r[k * 64 + c], s));
    out[(size_t)i * 64 + c] = s;
}

__global__ void noop_kernel() {}

extern "C" void kernel_launch(void* const* d_in, const int* in_sizes, int n_in,
                              void* d_out, int out_size) {
    const float* x   = (const float*)d_in[0];
    const float* W1l = (const float*)d_in[1];
    const float* W1r = (const float*)d_in[2];
    const float* W2l = (const float*)d_in[3];
    const float* W2r = (const float*)d_in[4];
    const int* es0   = (const int*)d_in[5];
    const int* ed0   = (const int*)d_in[6];
    const int* es1   = (const int*)d_in[7];
    const int* ed1   = (const int*)d_in[8];
    float* out = (float*)d_out;

    __nv_bfloat16* y;
    float *h, *agg0, *agg1, *cnt0, *cnt1;
    cudaGetSymbolAddress((void**)&y,    g_y);
    cudaGetSymbolAddress((void**)&h,    g_h);
    cudaGetSymbolAddress((void**)&agg0, g_agg0);
    cudaGetSymbolAddress((void**)&agg1, g_agg1);
    cudaGetSymbolAddress((void**)&cnt0, g_cnt0);
    cudaGetSymbolAddress((void**)&cnt1, g_cnt1);

    cudaMemsetAsync(agg0, 0, sizeof(float) * (size_t)N1 * 32, 0);
    cudaMemsetAsync(cnt0, 0, sizeof(float) * N1, 0);
    cudaMemsetAsync(agg1, 0, sizeof(float) * (size_t)N2 * 32, 0);
    cudaMemsetAsync(cnt1, 0, sizeof(float) * N2, 0);

    // kernel-launch order: #0,#1 noop, #2 gemm(N0), #3 scatter_bf16(E0) <- profiled
    noop_kernel<<<1, 32>>>();
    noop_kernel<<<1, 32>>>();

    gemm_mma_kernel<<<(N0 + 127) / 128, 256>>>(x, W1l, N0, y, nullptr, 0, nullptr, nullptr);
    scatter_bf16_kernel<<<(int)(((size_t)(E0 / 4) * 8 + 255) / 256), 256>>>(es0, ed0, y, agg0, cnt0, E0);
    gemm_mma_kernel<<<(N1 + 127) / 128, 256>>>(x, W1r, N1, nullptr, h, 1, agg0, cnt0);
    scatter_kernel<<<(int)(((size_t)(E1 / 4) * 8 + 255) / 256), 256>>>(es1, ed1, h, agg1, cnt1, E1);
    final_kernel<<<N2 / 4, 256>>>(agg1, cnt1, h, W2l, W2r, out);
}

// round 13
// speedup vs baseline: 1.0926x; 1.0080x over previous
#include <cuda_runtime.h>
#include <cuda_bf16.h>
#include <cstdint>
#include <cstddef>

#define N0 2000000
#define N1 200000
#define N2 16384
#define E0 3200000
#define E1 262144

// Scratch (device globals: allocation-free rule)
__device__ __nv_bfloat16 g_y[(size_t)N0 * 32];   // 128 MB, bf16-compressed
__device__ float g_h[(size_t)N1 * 32];
__device__ float g_agg0[(size_t)N1 * 32];
__device__ float g_agg1[(size_t)N2 * 32];
__device__ float g_cnt0[N1];
__device__ float g_cnt1[N2];

// pack two f32 -> bf16x2 word: low half = first arg, high half = second arg
__device__ __forceinline__ uint32_t pack_bf16x2(float lo, float hi) {
    uint32_t r;
    asm("cvt.rn.bf16x2.f32 %0, %1, %2;" : "=r"(r) : "f"(hi), "f"(lo));
    return r;
}
__device__ __forceinline__ float bf_lo(uint32_t w) { return __uint_as_float(w << 16); }
__device__ __forceinline__ float bf_hi(uint32_t w) { return __uint_as_float(w & 0xffff0000u); }

// D(16x8,f32) += A(16x16,bf16 row) * B(16x8,bf16 col)
__device__ __forceinline__ void mma16816(float* c, const uint32_t* a, const uint32_t* b) {
    asm volatile(
        "mma.sync.aligned.m16n8k16.row.col.f32.bf16.bf16.f32 "
        "{%0,%1,%2,%3}, {%4,%5,%6,%7}, {%8,%9}, {%0,%1,%2,%3};"
        : "+f"(c[0]), "+f"(c[1]), "+f"(c[2]), "+f"(c[3])
        : "r"(a[0]), "r"(a[1]), "r"(a[2]), "r"(a[3]), "r"(b[0]), "r"(b[1]));
}

// ---------------- HMMA GEMM: out[m,0..31] = x[m,0..127] @ W^T ----------------
// K-slot permutation: thread tig's k-slots (2t,2t+1,2t+8,2t+9) hold ACTUAL
// columns 4t..4t+3 (same permutation on A and B) -> A fragment = one LDG.128.
// bf16 split: keep hi*hi + hi*lo + lo*hi (~4e-6 rel err).
// mode 0: write bf16 y.  mode 1: out = relu(acc + agg/cnt) in fp32.
__global__ void __launch_bounds__(256) gemm_mma_kernel(
    const float* __restrict__ x, const float* __restrict__ W, int M,
    __nv_bfloat16* __restrict__ obf, float* __restrict__ out, int mode,
    const float* __restrict__ agg, const float* __restrict__ cnt)
{
    __shared__ uint32_t sBhi[8][4][32][2];   // 8 KB
    __shared__ uint32_t sBlo[8][4][32][2];   // 8 KB

    const int tid = threadIdx.x;
    const int warp = tid >> 5, lane = tid & 31;
    const int gid = lane >> 2, tig = lane & 3;

    // Build B fragments (permuted): lane l -> n = nt*8 + (l>>2), k0 = kt*16 + (l&3)*4
    for (int i = tid; i < 1024; i += 256) {
        int l = i & 31, nt = (i >> 5) & 3, kt = i >> 7;
        int n = nt * 8 + (l >> 2);
        int k0 = kt * 16 + (l & 3) * 4;
        float4 w = *reinterpret_cast<const float4*>(W + n * 128 + k0);
        uint32_t h0 = pack_bf16x2(w.x, w.y);
        uint32_t h1 = pack_bf16x2(w.z, w.w);
        sBhi[kt][nt][l][0] = h0;
        sBhi[kt][nt][l][1] = h1;
        sBlo[kt][nt][l][0] = pack_bf16x2(w.x - bf_lo(h0), w.y - bf_hi(h0));
        sBlo[kt][nt][l][1] = pack_bf16x2(w.z - bf_lo(h1), w.w - bf_hi(h1));
    }
    __syncthreads();

    int r0 = blockIdx.x * 128 + warp * 16 + gid;
    int r1 = r0 + 8;
    int r0c = r0 < M ? r0 : M - 1;
    int r1c = r1 < M ? r1 : M - 1;
    const float* x0 = x + (size_t)r0c * 128;
    const float* x1 = x + (size_t)r1c * 128;

    float acc[4][4];
#pragma unroll
    for (int nt = 0; nt < 4; ++nt)
#pragma unroll
        for (int j = 0; j < 4; ++j) acc[nt][j] = 0.f;

#pragma unroll
    for (int kt = 0; kt < 8; ++kt) {
        int c0 = kt * 16 + tig * 4;
        float4 f0 = *reinterpret_cast<const float4*>(x0 + c0);
        float4 f1 = *reinterpret_cast<const float4*>(x1 + c0);

        uint32_t ahi[4], alo[4];
        ahi[0] = pack_bf16x2(f0.x, f0.y);
        ahi[1] = pack_bf16x2(f1.x, f1.y);
        ahi[2] = pack_bf16x2(f0.z, f0.w);
        ahi[3] = pack_bf16x2(f1.z, f1.w);
        alo[0] = pack_bf16x2(f0.x - bf_lo(ahi[0]), f0.y - bf_hi(ahi[0]));
        alo[1] = pack_bf16x2(f1.x - bf_lo(ahi[1]), f1.y - bf_hi(ahi[1]));
        alo[2] = pack_bf16x2(f0.z - bf_lo(ahi[2]), f0.w - bf_hi(ahi[2]));
        alo[3] = pack_bf16x2(f1.z - bf_lo(ahi[3]), f1.w - bf_hi(ahi[3]));

#pragma unroll
        for (int nt = 0; nt < 4; ++nt) {
            uint32_t bh[2], bl[2];
            bh[0] = sBhi[kt][nt][lane][0];
            bh[1] = sBhi[kt][nt][lane][1];
            bl[0] = sBlo[kt][nt][lane][0];
            bl[1] = sBlo[kt][nt][lane][1];
            mma16816(acc[nt], ahi, bh);
            mma16816(acc[nt], ahi, bl);
            mma16816(acc[nt], alo, bh);
        }
    }

    // Epilogue. D frag: c0,c1 -> (r0, nt*8+tig*2..+1); c2,c3 -> (r1, same cols)
    if (mode == 0) {
        if (r0 < M) {
            uint32_t* o = reinterpret_cast<uint32_t*>(obf + (size_t)r0 * 32) + tig;
#pragma unroll
            for (int nt = 0; nt < 4; ++nt)
                o[nt * 4] = pack_bf16x2(acc[nt][0], acc[nt][1]);
        }
        if (r1 < M) {
            uint32_t* o = reinterpret_cast<uint32_t*>(obf + (size_t)r1 * 32) + tig;
#pragma unroll
            for (int nt = 0; nt < 4; ++nt)
                o[nt * 4] = pack_bf16x2(acc[nt][2], acc[nt][3]);
        }
    } else {
        if (r0 < M) {
            float inv = 1.0f / fmaxf(__ldg(cnt + r0), 1.0f);
            const float* g = agg + (size_t)r0 * 32 + tig * 2;
            float* o = out + (size_t)r0 * 32 + tig * 2;
#pragma unroll
            for (int nt = 0; nt < 4; ++nt) {
                float2 a = *reinterpret_cast<const float2*>(g + nt * 8);
                float2 v;
                v.x = fmaxf(fmaf(a.x, inv, acc[nt][0]), 0.f);
                v.y = fmaxf(fmaf(a.y, inv, acc[nt][1]), 0.f);
                *reinterpret_cast<float2*>(o + nt * 8) = v;
            }
        }
        if (r1 < M) {
            float inv = 1.0f / fmaxf(__ldg(cnt + r1), 1.0f);
            const float* g = agg + (size_t)r1 * 32 + tig * 2;
            float* o = out + (size_t)r1 * 32 + tig * 2;
#pragma unroll
            for (int nt = 0; nt < 4; ++nt) {
                float2 a = *reinterpret_cast<const float2*>(g + nt * 8);
                float2 v;
                v.x = fmaxf(fmaf(a.x, inv, acc[nt][2]), 0.f);
                v.y = fmaxf(fmaf(a.y, inv, acc[nt][3]), 0.f);
                *reinterpret_cast<float2*>(o + nt * 8) = v;
            }
        }
    }
}

// ---------------- bf16 edge scatter: 8 threads/edge, 8-edge MLP ----------------
// Per edge-part: one uint2 gather (8 B) + one float4 RED. All 8 gathers issued
// before any atomic -> 8 outstanding random lines per thread.
__global__ void scatter_bf16_kernel(const int* __restrict__ src, const int* __restrict__ dst,
                                    const __nv_bfloat16* __restrict__ feat,
                                    float* __restrict__ agg, float* __restrict__ cnt, int E) {
    int g = blockIdx.x * blockDim.x + threadIdx.x;
    int oct = E >> 3;
    int e = g >> 3, part = g & 7;
    if (e >= oct) return;
    int s[8], d[8];
#pragma unroll
    for (int j = 0; j < 8; ++j) {
        s[j] = __ldg(src + e + j * oct);
        d[j] = __ldg(dst + e + j * oct);
    }
    uint2 v[8];
#pragma unroll
    for (int j = 0; j < 8; ++j)
        v[j] = reinterpret_cast<const uint2*>(feat + (size_t)s[j] * 32)[part];
#pragma unroll
    for (int j = 0; j < 8; ++j) {
        float4 f = make_float4(bf_lo(v[j].x), bf_hi(v[j].x), bf_lo(v[j].y), bf_hi(v[j].y));
        atomicAdd(reinterpret_cast<float4*>(agg + (size_t)d[j] * 32 + part * 4), f);
    }
    if (part == 0) {
#pragma unroll
        for (int j = 0; j < 8; ++j) atomicAdd(cnt + d[j], 1.0f);
    }
}

// ---------------- fp32 edge scatter (8 threads/edge, 4-edge MLP) — for h/E1 ----------------
__global__ void scatter_kernel(const int* __restrict__ src, const int* __restrict__ dst,
                               const float* __restrict__ feat, float* __restrict__ agg,
                               float* __restrict__ cnt, int E) {
    int g = blockIdx.x * blockDim.x + threadIdx.x;
    int quart = E >> 2;
    int e = g >> 3, part = g & 7;
    if (e >= quart) return;
    int s[4], d[4];
#pragma unroll
    for (int j = 0; j < 4; ++j) {
        s[j] = __ldg(src + e + j * quart);
        d[j] = __ldg(dst + e + j * quart);
    }
    float4 v[4];
#pragma unroll
    for (int j = 0; j < 4; ++j)
        v[j] = *reinterpret_cast<const float4*>(feat + (size_t)s[j] * 32 + part * 4);
#pragma unroll
    for (int j = 0; j < 4; ++j)
        atomicAdd(reinterpret_cast<float4*>(agg + (size_t)d[j] * 32 + part * 4), v[j]);
    if (part == 0) {
#pragma unroll
        for (int j = 0; j < 4; ++j) atomicAdd(cnt + d[j], 1.0f);
    }
}

// ---------------- layer-1 combine ----------------
__global__ void final_kernel(const float* __restrict__ agg1, const float* __restrict__ cnt1,
                             const float* __restrict__ h, const float* __restrict__ W2l,
                             const float* __restrict__ W2r, float* __restrict__ out) {
    __shared__ float s2l[32 * 64];
    __shared__ float s2r[32 * 64];
    int tid = threadIdx.x;
    for (int idx = tid; idx < 2048; idx += 256) {
        int c = idx >> 5, k = idx & 31;
        s2l[k * 64 + c] = W2l[idx];
        s2r[k * 64 + c] = W2r[idx];
    }
    __syncthreads();
    int i = blockIdx.x * 4 + (tid >> 6);
    int c = tid & 63;
    float inv = 1.0f / fmaxf(__ldg(cnt1 + i), 1.0f);
    const float* ag = agg1 + (size_t)i * 32;
    const float* hh = h + (size_t)i * 32;
    float s = 0.f;
#pragma unroll
    for (int k = 0; k < 32; ++k)
        s = fmaf(__ldg(ag + k) * inv, s2l[k * 64 + c], fmaf(__ldg(hh + k), s2r[k * 64 + c], s));
    out[(size_t)i * 64 + c] = s;
}

__global__ void noop_kernel() {}

extern "C" void kernel_launch(void* const* d_in, const int* in_sizes, int n_in,
                              void* d_out, int out_size) {
    const float* x   = (const float*)d_in[0];
    const float* W1l = (const float*)d_in[1];
    const float* W1r = (const float*)d_in[2];
    const float* W2l = (const float*)d_in[3];
    const float* W2r = (const float*)d_in[4];
    const int* es0   = (const int*)d_in[5];
    const int* ed0   = (const int*)d_in[6];
    const int* es1   = (const int*)d_in[7];
    const int* ed1   = (const int*)d_in[8];
    float* out = (float*)d_out;

    __nv_bfloat16* y;
    float *h, *agg0, *agg1, *cnt0, *cnt1;
    cudaGetSymbolAddress((void**)&y,    g_y);
    cudaGetSymbolAddress((void**)&h,    g_h);
    cudaGetSymbolAddress((void**)&agg0, g_agg0);
    cudaGetSymbolAddress((void**)&agg1, g_agg1);
    cudaGetSymbolAddress((void**)&cnt0, g_cnt0);
    cudaGetSymbolAddress((void**)&cnt1, g_cnt1);

    cudaMemsetAsync(agg0, 0, sizeof(float) * (size_t)N1 * 32, 0);
    cudaMemsetAsync(cnt0, 0, sizeof(float) * N1, 0);
    cudaMemsetAsync(agg1, 0, sizeof(float) * (size_t)N2 * 32, 0);
    cudaMemsetAsync(cnt1, 0, sizeof(float) * N2, 0);

    // kernel-launch order: #0..#2 noop, #3 gemm(N0) <- profiled
    noop_kernel<<<1, 32>>>();
    noop_kernel<<<1, 32>>>();
    noop_kernel<<<1, 32>>>();

    gemm_mma_kernel<<<(N0 + 127) / 128, 256>>>(x, W1l, N0, y, nullptr, 0, nullptr, nullptr);
    scatter_bf16_kernel<<<(int)(((size_t)(E0 / 8) * 8 + 255) / 256), 256>>>(es0, ed0, y, agg0, cnt0, E0);
    gemm_mma_kernel<<<(N1 + 127) / 128, 256>>>(x, W1r, N1, nullptr, h, 1, agg0, cnt0);
    scatter_kernel<<<(int)(((size_t)(E1 / 4) * 8 + 255) / 256), 256>>>(es1, ed1, h, agg1, cnt1, E1);
    final_kernel<<<N2 / 4, 256>>>(agg1, cnt1, h, W2l, W2r, out);
}

// round 14
// speedup vs baseline: 1.1100x; 1.0159x over previous
#include <cuda_runtime.h>
#include <cuda_bf16.h>
#include <cstdint>
#include <cstddef>

#define N0 2000000
#define N1 200000
#define N2 16384
#define E0 3200000
#define E1 262144
#define SPLIT 200064   // 1563*128; DUAL kernel covers [0,SPLIT), plain covers [SPLIT,N0)

// Scratch (device globals: allocation-free rule)
__device__ __nv_bfloat16 g_y[(size_t)N0 * 32];   // 128 MB, bf16
__device__ float g_yr[(size_t)N1 * 32];          // x[:N1] @ W1r^T, fp32
__device__ float g_h[(size_t)N1 * 32];
__device__ float g_agg0[(size_t)N1 * 32];
__device__ float g_agg1[(size_t)N2 * 32];
__device__ float g_cnt0[N1];
__device__ float g_cnt1[N2];

__device__ __forceinline__ uint32_t pack_bf16x2(float lo, float hi) {
    uint32_t r;
    asm("cvt.rn.bf16x2.f32 %0, %1, %2;" : "=r"(r) : "f"(hi), "f"(lo));
    return r;
}
__device__ __forceinline__ float bf_lo(uint32_t w) { return __uint_as_float(w << 16); }
__device__ __forceinline__ float bf_hi(uint32_t w) { return __uint_as_float(w & 0xffff0000u); }

__device__ __forceinline__ void mma16816(float* c, const uint32_t* a, const uint32_t* b) {
    asm volatile(
        "mma.sync.aligned.m16n8k16.row.col.f32.bf16.bf16.f32 "
        "{%0,%1,%2,%3}, {%4,%5,%6,%7}, {%8,%9}, {%0,%1,%2,%3};"
        : "+f"(c[0]), "+f"(c[1]), "+f"(c[2]), "+f"(c[3])
        : "r"(a[0]), "r"(a[1]), "r"(a[2]), "r"(a[3]), "r"(b[0]), "r"(b[1]));
}

// ---------------- HMMA GEMM (K-slot permuted; bf16 split hi/lo) ----------------
// DUAL=false: y[m] = x[m] @ Wl^T  (bf16 out), rows [base, base+grid*128)
// DUAL=true : additionally yr[m] = x[m] @ Wr^T (fp32 out) for m < N1
template <bool DUAL>
__global__ void __launch_bounds__(256) gemm_mma_kernel(
    const float* __restrict__ x, const float* __restrict__ Wl,
    const float* __restrict__ Wr, int base, int M,
    __nv_bfloat16* __restrict__ obf, float* __restrict__ oyr)
{
    __shared__ uint32_t sBhi[8][4][32][2];
    __shared__ uint32_t sBlo[8][4][32][2];
    __shared__ uint32_t sB2hi[DUAL ? 8 : 1][4][32][2];
    __shared__ uint32_t sB2lo[DUAL ? 8 : 1][4][32][2];

    const int tid = threadIdx.x;
    const int warp = tid >> 5, lane = tid & 31;
    const int gid = lane >> 2, tig = lane & 3;

    for (int i = tid; i < 1024; i += 256) {
        int l = i & 31, nt = (i >> 5) & 3, kt = i >> 7;
        int n = nt * 8 + (l >> 2);
        int k0 = kt * 16 + (l & 3) * 4;
        float4 w = *reinterpret_cast<const float4*>(Wl + n * 128 + k0);
        uint32_t h0 = pack_bf16x2(w.x, w.y);
        uint32_t h1 = pack_bf16x2(w.z, w.w);
        sBhi[kt][nt][l][0] = h0;
        sBhi[kt][nt][l][1] = h1;
        sBlo[kt][nt][l][0] = pack_bf16x2(w.x - bf_lo(h0), w.y - bf_hi(h0));
        sBlo[kt][nt][l][1] = pack_bf16x2(w.z - bf_lo(h1), w.w - bf_hi(h1));
        if (DUAL) {
            float4 w2 = *reinterpret_cast<const float4*>(Wr + n * 128 + k0);
            uint32_t g0 = pack_bf16x2(w2.x, w2.y);
            uint32_t g1 = pack_bf16x2(w2.z, w2.w);
            sB2hi[kt][nt][l][0] = g0;
            sB2hi[kt][nt][l][1] = g1;
            sB2lo[kt][nt][l][0] = pack_bf16x2(w2.x - bf_lo(g0), w2.y - bf_hi(g0));
            sB2lo[kt][nt][l][1] = pack_bf16x2(w2.z - bf_lo(g1), w2.w - bf_hi(g1));
        }
    }
    __syncthreads();

    int r0 = base + blockIdx.x * 128 + warp * 16 + gid;
    int r1 = r0 + 8;
    int r0c = r0 < M ? r0 : M - 1;
    int r1c = r1 < M ? r1 : M - 1;
    const float* x0 = x + (size_t)r0c * 128;
    const float* x1 = x + (size_t)r1c * 128;

    float acc[4][4];
    float acc2[DUAL ? 4 : 1][DUAL ? 4 : 1];
#pragma unroll
    for (int nt = 0; nt < 4; ++nt)
#pragma unroll
        for (int j = 0; j < 4; ++j) acc[nt][j] = 0.f;
    if (DUAL) {
#pragma unroll
        for (int nt = 0; nt < 4; ++nt)
#pragma unroll
            for (int j = 0; j < 4; ++j) acc2[nt][j] = 0.f;
    }

#pragma unroll
    for (int kt = 0; kt < 8; ++kt) {
        int c0 = kt * 16 + tig * 4;
        float4 f0 = *reinterpret_cast<const float4*>(x0 + c0);
        float4 f1 = *reinterpret_cast<const float4*>(x1 + c0);

        uint32_t ahi[4], alo[4];
        ahi[0] = pack_bf16x2(f0.x, f0.y);
        ahi[1] = pack_bf16x2(f1.x, f1.y);
        ahi[2] = pack_bf16x2(f0.z, f0.w);
        ahi[3] = pack_bf16x2(f1.z, f1.w);
        alo[0] = pack_bf16x2(f0.x - bf_lo(ahi[0]), f0.y - bf_hi(ahi[0]));
        alo[1] = pack_bf16x2(f1.x - bf_lo(ahi[1]), f1.y - bf_hi(ahi[1]));
        alo[2] = pack_bf16x2(f0.z - bf_lo(ahi[2]), f0.w - bf_hi(ahi[2]));
        alo[3] = pack_bf16x2(f1.z - bf_lo(ahi[3]), f1.w - bf_hi(ahi[3]));

#pragma unroll
        for (int nt = 0; nt < 4; ++nt) {
            uint32_t bh[2], bl[2];
            bh[0] = sBhi[kt][nt][lane][0];
            bh[1] = sBhi[kt][nt][lane][1];
            bl[0] = sBlo[kt][nt][lane][0];
            bl[1] = sBlo[kt][nt][lane][1];
            mma16816(acc[nt], ahi, bh);
            mma16816(acc[nt], ahi, bl);
            mma16816(acc[nt], alo, bh);
            if (DUAL) {
                uint32_t ch[2], cl[2];
                ch[0] = sB2hi[kt][nt][lane][0];
                ch[1] = sB2hi[kt][nt][lane][1];
                cl[0] = sB2lo[kt][nt][lane][0];
                cl[1] = sB2lo[kt][nt][lane][1];
                mma16816(acc2[nt], ahi, ch);
                mma16816(acc2[nt], ahi, cl);
                mma16816(acc2[nt], alo, ch);
            }
        }
    }

    // y store (bf16). D frag: c0,c1 -> (r0, nt*8+tig*2..+1); c2,c3 -> (r1, same)
    if (r0 < M) {
        uint32_t* o = reinterpret_cast<uint32_t*>(obf + (size_t)r0 * 32) + tig;
#pragma unroll
        for (int nt = 0; nt < 4; ++nt) o[nt * 4] = pack_bf16x2(acc[nt][0], acc[nt][1]);
    }
    if (r1 < M) {
        uint32_t* o = reinterpret_cast<uint32_t*>(obf + (size_t)r1 * 32) + tig;
#pragma unroll
        for (int nt = 0; nt < 4; ++nt) o[nt * 4] = pack_bf16x2(acc[nt][2], acc[nt][3]);
    }
    if (DUAL) {
        if (r0 < N1) {
            float* o = oyr + (size_t)r0 * 32 + tig * 2;
#pragma unroll
            for (int nt = 0; nt < 4; ++nt)
                *reinterpret_cast<float2*>(o + nt * 8) = make_float2(acc2[nt][0], acc2[nt][1]);
        }
        if (r1 < N1) {
            float* o = oyr + (size_t)r1 * 32 + tig * 2;
#pragma unroll
            for (int nt = 0; nt < 4; ++nt)
                *reinterpret_cast<float2*>(o + nt * 8) = make_float2(acc2[nt][2], acc2[nt][3]);
        }
    }
}

// ---------------- bf16 edge scatter: 8 threads/edge, 8-edge MLP ----------------
__global__ void scatter_bf16_kernel(const int* __restrict__ src, const int* __restrict__ dst,
                                    const __nv_bfloat16* __restrict__ feat,
                                    float* __restrict__ agg, float* __restrict__ cnt, int E) {
    int g = blockIdx.x * blockDim.x + threadIdx.x;
    int oct = E >> 3;
    int e = g >> 3, part = g & 7;
    if (e >= oct) return;
    int s[8], d[8];
#pragma unroll
    for (int j = 0; j < 8; ++j) {
        s[j] = __ldg(src + e + j * oct);
        d[j] = __ldg(dst + e + j * oct);
    }
    uint2 v[8];
#pragma unroll
    for (int j = 0; j < 8; ++j)
        v[j] = reinterpret_cast<const uint2*>(feat + (size_t)s[j] * 32)[part];
#pragma unroll
    for (int j = 0; j < 8; ++j) {
        float4 f = make_float4(bf_lo(v[j].x), bf_hi(v[j].x), bf_lo(v[j].y), bf_hi(v[j].y));
        atomicAdd(reinterpret_cast<float4*>(agg + (size_t)d[j] * 32 + part * 4), f);
    }
    if (part == 0) {
#pragma unroll
        for (int j = 0; j < 8; ++j) atomicAdd(cnt + d[j], 1.0f);
    }
}

// ---------------- fp32 edge scatter (8 threads/edge, 4-edge MLP) — for h/E1 ----------------
__global__ void scatter_kernel(const int* __restrict__ src, const int* __restrict__ dst,
                               const float* __restrict__ feat, float* __restrict__ agg,
                               float* __restrict__ cnt, int E) {
    int g = blockIdx.x * blockDim.x + threadIdx.x;
    int quart = E >> 2;
    int e = g >> 3, part = g & 7;
    if (e >= quart) return;
    int s[4], d[4];
#pragma unroll
    for (int j = 0; j < 4; ++j) {
        s[j] = __ldg(src + e + j * quart);
        d[j] = __ldg(dst + e + j * quart);
    }
    float4 v[4];
#pragma unroll
    for (int j = 0; j < 4; ++j)
        v[j] = *reinterpret_cast<const float4*>(feat + (size_t)s[j] * 32 + part * 4);
#pragma unroll
    for (int j = 0; j < 4; ++j)
        atomicAdd(reinterpret_cast<float4*>(agg + (size_t)d[j] * 32 + part * 4), v[j]);
    if (part == 0) {
#pragma unroll
        for (int j = 0; j < 4; ++j) atomicAdd(cnt + d[j], 1.0f);
    }
}

// ---------------- h = relu(agg0/cnt + yr), elementwise float4 ----------------
__global__ void relu_combine_kernel(const float* __restrict__ agg, const float* __restrict__ cnt,
                                    const float* __restrict__ yr, float* __restrict__ h) {
    int i = blockIdx.x * blockDim.x + threadIdx.x;   // float4 index, N1*8 total
    if (i >= N1 * 8) return;
    int row = i >> 3;
    float inv = 1.0f / fmaxf(__ldg(cnt + row), 1.0f);
    float4 a = reinterpret_cast<const float4*>(agg)[i];
    float4 v = reinterpret_cast<const float4*>(yr)[i];
    float4 r;
    r.x = fmaxf(fmaf(a.x, inv, v.x), 0.f);
    r.y = fmaxf(fmaf(a.y, inv, v.y), 0.f);
    r.z = fmaxf(fmaf(a.z, inv, v.z), 0.f);
    r.w = fmaxf(fmaf(a.w, inv, v.w), 0.f);
    reinterpret_cast<float4*>(h)[i] = r;
}

// ---------------- layer-1 combine ----------------
__global__ void final_kernel(const float* __restrict__ agg1, const float* __restrict__ cnt1,
                             const float* __restrict__ h, const float* __restrict__ W2l,
                             const float* __restrict__ W2r, float* __restrict__ out) {
    __shared__ float s2l[32 * 64];
    __shared__ float s2r[32 * 64];
    int tid = threadIdx.x;
    for (int idx = tid; idx < 2048; idx += 256) {
        int c = idx >> 5, k = idx & 31;
        s2l[k * 64 + c] = W2l[idx];
        s2r[k * 64 + c] = W2r[idx];
    }
    __syncthreads();
    int i = blockIdx.x * 4 + (tid >> 6);
    int c = tid & 63;
    float inv = 1.0f / fmaxf(__ldg(cnt1 + i), 1.0f);
    const float* ag = agg1 + (size_t)i * 32;
    const float* hh = h + (size_t)i * 32;
    float s = 0.f;
#pragma unroll
    for (int k = 0; k < 32; ++k)
        s = fmaf(__ldg(ag + k) * inv, s2l[k * 64 + c], fmaf(__ldg(hh + k), s2r[k * 64 + c], s));
    out[(size_t)i * 64 + c] = s;
}

extern "C" void kernel_launch(void* const* d_in, const int* in_sizes, int n_in,
                              void* d_out, int out_size) {
    const float* x   = (const float*)d_in[0];
    const float* W1l = (const float*)d_in[1];
    const float* W1r = (const float*)d_in[2];
    const float* W2l = (const float*)d_in[3];
    const float* W2r = (const float*)d_in[4];
    const int* es0   = (const int*)d_in[5];
    const int* ed0   = (const int*)d_in[6];
    const int* es1   = (const int*)d_in[7];
    const int* ed1   = (const int*)d_in[8];
    float* out = (float*)d_out;

    __nv_bfloat16* y;
    float *yr, *h, *agg0, *agg1, *cnt0, *cnt1;
    cudaGetSymbolAddress((void**)&y,    g_y);
    cudaGetSymbolAddress((void**)&yr,   g_yr);
    cudaGetSymbolAddress((void**)&h,    g_h);
    cudaGetSymbolAddress((void**)&agg0, g_agg0);
    cudaGetSymbolAddress((void**)&agg1, g_agg1);
    cudaGetSymbolAddress((void**)&cnt0, g_cnt0);
    cudaGetSymbolAddress((void**)&cnt1, g_cnt1);

    cudaMemsetAsync(agg0, 0, sizeof(float) * (size_t)N1 * 32, 0);
    cudaMemsetAsync(cnt0, 0, sizeof(float) * N1, 0);
    cudaMemsetAsync(agg1, 0, sizeof(float) * (size_t)N2 * 32, 0);
    cudaMemsetAsync(cnt1, 0, sizeof(float) * N2, 0);

    // DUAL: rows [0, SPLIT) -> y(bf16) + yr(fp32); plain: rows [SPLIT, N0) -> y
    gemm_mma_kernel<true><<<SPLIT / 128, 256>>>(x, W1l, W1r, 0, N0, y, yr);
    gemm_mma_kernel<false><<<(N0 - SPLIT) / 128, 256>>>(x, W1l, nullptr, SPLIT, N0, y, nullptr);
    // sum y over E0 edges
    scatter_bf16_kernel<<<(int)(((size_t)(E0 / 8) * 8 + 255) / 256), 256>>>(es0, ed0, y, agg0, cnt0, E0);
    // h = relu(agg0/cnt + yr)
    relu_combine_kernel<<<(N1 * 8 + 255) / 256, 256>>>(agg0, cnt0, yr, h);
    // layer-1 aggregation + combine
    scatter_kernel<<<(int)(((size_t)(E1 / 4) * 8 + 255) / 256), 256>>>(es1, ed1, h, agg1, cnt1, E1);
    final_kernel<<<N2 / 4, 256>>>(agg1, cnt1, h, W2l, W2r, out);
}